// round 3
// baseline (speedup 1.0000x reference)
#include <cuda_runtime.h>

#define BB      4096
#define DD      8192
#define KK      5
#define GS      40
#define CKLEN   17     // 4 composed 5-tap kernels -> 17 taps
#define NTHR    256
#define OUT_PER_THR 8
#define TILE    (NTHR * OUT_PER_THR)   // 2048
#define TILES_PER_ROW (DD / TILE)      // 4

// Scratch: composed per-row 17-tap kernels (4096 * 17 * 4B = 278 KB, L2-resident)
__device__ float g_ck[BB * CKLEN];

// ---------------------------------------------------------------------------
// Kernel 1: compute max_it (batch-global) and compose each row's 17-tap kernel.
// One block of 256 threads; ~2-3 us of work total.
// ---------------------------------------------------------------------------
__global__ void __launch_bounds__(NTHR)
compose_kernel(const int* __restrict__ g, const float* __restrict__ kernels)
{
    __shared__ int s_red[NTHR / 32];
    const int t = threadIdx.x;

    // --- reduce max_it = max over b of g[b] / GS   (g >= 0 in this problem) ---
    int m = 0;
    for (int i = t; i < BB; i += NTHR) {
        int gv = g[i];
        int av = gv < 0 ? -gv : gv;     // defensive abs (matches jnp.abs)
        m = max(m, av / GS);
    }
    #pragma unroll
    for (int o = 16; o > 0; o >>= 1)
        m = max(m, __shfl_xor_sync(0xffffffffu, m, o));
    if ((t & 31) == 0) s_red[t >> 5] = m;
    __syncthreads();
    int max_it = s_red[0];
    #pragma unroll
    for (int w = 1; w < NTHR / 32; w++) max_it = max(max_it, s_red[w]);

    // --- shared kernel rows: id_k = kernels[40], pos max_k = kernels[80] ---
    float idk[KK], posk[KK], negk[KK];
    #pragma unroll
    for (int j = 0; j < KK; j++) {
        idk[j]  = kernels[40 * KK + j];
        posk[j] = kernels[80 * KK + j];
        negk[j] = kernels[0  * KK + j];  // sign = -1 case (unused for g>=0, kept for safety)
    }

    // --- per-row composition ---
    for (int b = t; b < BB; b += NTHR) {
        int gv  = g[b];
        int sgn = (gv > 0) - (gv < 0);          // jnp.sign
        int av  = gv < 0 ? -gv : gv;
        int it  = av / GS;
        int rem = av - it * GS;

        // final kernel = kernels[rem*sgn + 40]
        int fidx = rem * sgn + 40;
        float fink[KK];
        #pragma unroll
        for (int j = 0; j < KK; j++) fink[j] = kernels[fidx * KK + j];

        // max_k = kernels[sgn*40 + 40]
        float maxk[KK];
        #pragma unroll
        for (int j = 0; j < KK; j++)
            maxk[j] = (sgn > 0) ? posk[j] : ((sgn < 0) ? negk[j] : idk[j]);

        // start with delta operator (offset 0 -> index 8)
        float c[CKLEN];
        #pragma unroll
        for (int p = 0; p < CKLEN; p++) c[p] = 0.f;
        c[8] = 1.f;

        // 3 loop stages + final. Correlation composition:
        //   c'[p] = sum_j kk[j] * c[p - j + 2]
        #pragma unroll
        for (int stage = 0; stage < 4; stage++) {
            float kk[KK];
            bool skip = false;
            if (stage == 3) {
                #pragma unroll
                for (int j = 0; j < KK; j++) kk[j] = fink[j];
            } else if (stage < it) {
                #pragma unroll
                for (int j = 0; j < KK; j++) kk[j] = maxk[j];
            } else if (stage < max_it) {
                #pragma unroll
                for (int j = 0; j < KK; j++) kk[j] = idk[j];
            } else {
                skip = true;   // exact delta -> identity, skip
            }
            if (!skip) {
                float nc[CKLEN];
                #pragma unroll
                for (int p = 0; p < CKLEN; p++) {
                    float a = 0.f;
                    #pragma unroll
                    for (int j = 0; j < KK; j++) {
                        int q = p - j + 2;
                        if (q >= 0 && q < CKLEN) a = fmaf(kk[j], c[q], a);
                    }
                    nc[p] = a;
                }
                #pragma unroll
                for (int p = 0; p < CKLEN; p++) c[p] = nc[p];
            }
        }

        #pragma unroll
        for (int p = 0; p < CKLEN; p++) g_ck[b * CKLEN + p] = c[p];
    }
}

// ---------------------------------------------------------------------------
// Kernel 2: single-pass 17-tap circular correlation per row.
// out[b][d] = sum_{p=0..16} ck[b][p] * x[b][(d + p - 8) mod D]
// Each thread: 8 contiguous outputs, window of 24 floats in registers.
// ---------------------------------------------------------------------------
__global__ void __launch_bounds__(NTHR)
conv_main(const float* __restrict__ x, float* __restrict__ out)
{
    const int bid  = blockIdx.x;
    const int b    = bid / TILES_PER_ROW;
    const int tile = bid - b * TILES_PER_ROW;
    const int d0   = tile * TILE + threadIdx.x * OUT_PER_THR;

    const float* __restrict__ xr = x + (size_t)b * DD;

    float w[OUT_PER_THR + CKLEN - 1];   // 24 floats: x[d0-8 .. d0+15]

    if (d0 >= 8 && d0 + 16 <= DD) {
        // fast path: 6 aligned float4 loads (d0-8 is a multiple of 8)
        const float4* p = reinterpret_cast<const float4*>(xr + d0 - 8);
        #pragma unroll
        for (int q = 0; q < 6; q++) {
            float4 v = p[q];
            w[4 * q + 0] = v.x;
            w[4 * q + 1] = v.y;
            w[4 * q + 2] = v.z;
            w[4 * q + 3] = v.w;
        }
    } else {
        // wrap path: only 2 threads per row land here
        #pragma unroll
        for (int i = 0; i < 24; i++) {
            int idx = d0 - 8 + i;
            idx = (idx < 0) ? idx + DD : ((idx >= DD) ? idx - DD : idx);
            w[i] = xr[idx];
        }
    }

    // broadcast load of the row's composed kernel (same addr across warp)
    float k[CKLEN];
    const float* ckp = g_ck + b * CKLEN;
    #pragma unroll
    for (int j = 0; j < CKLEN; j++) k[j] = __ldg(ckp + j);

    float acc[OUT_PER_THR];
    #pragma unroll
    for (int u = 0; u < OUT_PER_THR; u++) {
        float a = 0.f;
        #pragma unroll
        for (int j = 0; j < CKLEN; j++)
            a = fmaf(k[j], w[u + j], a);
        acc[u] = a;
    }

    float4* o = reinterpret_cast<float4*>(out + (size_t)b * DD + d0);
    o[0] = make_float4(acc[0], acc[1], acc[2], acc[3]);
    o[1] = make_float4(acc[4], acc[5], acc[6], acc[7]);
}

// ---------------------------------------------------------------------------
// Launch
// ---------------------------------------------------------------------------
extern "C" void kernel_launch(void* const* d_in, const int* in_sizes, int n_in,
                              void* d_out, int out_size)
{
    const float* x       = (const float*)d_in[0];   // [4096, 8192] f32
    const int*   g       = (const int*)  d_in[1];   // [4096] i32
    const float* kernels = (const float*)d_in[2];   // [81, 5] f32
    float*       out     = (float*)d_out;           // [4096, 1, 8192] f32

    compose_kernel<<<1, NTHR>>>(g, kernels);
    conv_main<<<BB * TILES_PER_ROW, NTHR>>>(x, out);
}

// round 4
// speedup vs baseline: 1.3533x; 1.3533x over previous
#include <cuda_runtime.h>

#define BB      4096
#define DD      8192
#define KK      5
#define GS      40
#define CKLEN   17     // 4 composed 5-tap kernels -> 17 taps
#define NTHR    256
#define OUT_PER_THR 16
#define TILE    (NTHR * OUT_PER_THR)   // 4096
#define TILES_PER_ROW (DD / TILE)      // 2

// Scratch: composed per-row 17-tap kernels (4096 * 17 * 4B = 278 KB, L2-resident)
__device__ float g_ck[BB * CKLEN];

// ---------------------------------------------------------------------------
// Kernel 1: compose each row's 17-tap kernel. 16 blocks x 256 threads,
// one row per thread. Each block redundantly reduces max_it over g (L2 hits).
// ---------------------------------------------------------------------------
__global__ void __launch_bounds__(NTHR)
compose_kernel(const int* __restrict__ g, const float* __restrict__ kernels)
{
    __shared__ int s_red[NTHR / 32];
    const int t = threadIdx.x;
    const int b = blockIdx.x * NTHR + t;   // grid = BB/NTHR blocks

    // --- block-redundant reduce: max_it = max over all b of |g[b]| / GS ---
    int m = 0;
    #pragma unroll 4
    for (int i = t; i < BB; i += NTHR) {
        int gv = g[i];
        int av = gv < 0 ? -gv : gv;
        m = max(m, av / GS);
    }
    #pragma unroll
    for (int o = 16; o > 0; o >>= 1)
        m = max(m, __shfl_xor_sync(0xffffffffu, m, o));
    if ((t & 31) == 0) s_red[t >> 5] = m;
    __syncthreads();
    int max_it = s_red[0];
    #pragma unroll
    for (int w = 1; w < NTHR / 32; w++) max_it = max(max_it, s_red[w]);

    // --- shared kernel rows ---
    float idk[KK], posk[KK], negk[KK];
    #pragma unroll
    for (int j = 0; j < KK; j++) {
        idk[j]  = __ldg(kernels + 40 * KK + j);
        posk[j] = __ldg(kernels + 80 * KK + j);
        negk[j] = __ldg(kernels + 0  * KK + j);
    }

    // --- this thread's row ---
    int gv  = g[b];
    int sgn = (gv > 0) - (gv < 0);          // jnp.sign
    int av  = gv < 0 ? -gv : gv;
    int it  = av / GS;
    int rem = av - it * GS;

    // final kernel = kernels[rem*sgn + 40]
    int fidx = rem * sgn + 40;
    float fink[KK];
    #pragma unroll
    for (int j = 0; j < KK; j++) fink[j] = __ldg(kernels + fidx * KK + j);

    float maxk[KK];
    #pragma unroll
    for (int j = 0; j < KK; j++)
        maxk[j] = (sgn > 0) ? posk[j] : ((sgn < 0) ? negk[j] : idk[j]);

    // start with delta operator (offset 0 -> index 8)
    float c[CKLEN];
    #pragma unroll
    for (int p = 0; p < CKLEN; p++) c[p] = 0.f;
    c[8] = 1.f;

    // 3 loop stages + final. Correlation composition: c'[p] = sum_j kk[j]*c[p-j+2]
    #pragma unroll
    for (int stage = 0; stage < 4; stage++) {
        float kk[KK];
        bool skip = false;
        if (stage == 3) {
            #pragma unroll
            for (int j = 0; j < KK; j++) kk[j] = fink[j];
        } else if (stage < it) {
            #pragma unroll
            for (int j = 0; j < KK; j++) kk[j] = maxk[j];
        } else if (stage < max_it) {
            #pragma unroll
            for (int j = 0; j < KK; j++) kk[j] = idk[j];
        } else {
            skip = true;   // exact delta -> identity, skip
        }
        if (!skip) {
            float nc[CKLEN];
            #pragma unroll
            for (int p = 0; p < CKLEN; p++) {
                float a = 0.f;
                #pragma unroll
                for (int j = 0; j < KK; j++) {
                    int q = p - j + 2;
                    if (q >= 0 && q < CKLEN) a = fmaf(kk[j], c[q], a);
                }
                nc[p] = a;
            }
            #pragma unroll
            for (int p = 0; p < CKLEN; p++) c[p] = nc[p];
        }
    }

    #pragma unroll
    for (int p = 0; p < CKLEN; p++) g_ck[b * CKLEN + p] = c[p];
}

// ---------------------------------------------------------------------------
// Kernel 2: single-pass 17-tap circular correlation per row.
// out[b][d] = sum_{p=0..16} ck[b][p] * x[b][(d + p - 8) mod D]
// Each thread: 16 contiguous outputs, window of 32 floats, two-phase compute
// so the first 8 window regs die before the second accumulator set goes live.
// ---------------------------------------------------------------------------
__global__ void __launch_bounds__(NTHR)
conv_main(const float* __restrict__ x, float* __restrict__ out)
{
    const int bid  = blockIdx.x;
    const int b    = bid >> 1;              // TILES_PER_ROW = 2
    const int tile = bid & 1;
    const int d0   = tile * TILE + threadIdx.x * OUT_PER_THR;

    const float* __restrict__ xr = x + (size_t)b * DD;

    float w[OUT_PER_THR + CKLEN - 1];       // 32 floats: x[d0-8 .. d0+23]

    if (d0 >= 8 && d0 + 24 <= DD) {
        // fast path: 8 aligned float4 loads (d0-8 is a multiple of 8)
        const float4* p = reinterpret_cast<const float4*>(xr + d0 - 8);
        #pragma unroll
        for (int q = 0; q < 8; q++) {
            float4 v = __ldg(p + q);
            w[4 * q + 0] = v.x;
            w[4 * q + 1] = v.y;
            w[4 * q + 2] = v.z;
            w[4 * q + 3] = v.w;
        }
    } else {
        // wrap path: only 2 threads per row land here
        #pragma unroll
        for (int i = 0; i < OUT_PER_THR + CKLEN - 1; i++) {
            int idx = d0 - 8 + i;
            idx = (idx < 0) ? idx + DD : ((idx >= DD) ? idx - DD : idx);
            w[i] = xr[idx];
        }
    }

    // row kernel: uniform across the whole block (one row per block)
    float k[CKLEN];
    const float* ckp = g_ck + b * CKLEN;
    #pragma unroll
    for (int j = 0; j < CKLEN; j++) k[j] = __ldg(ckp + j);

    float4* o = reinterpret_cast<float4*>(out + (size_t)b * DD + d0);

    // phase A: outputs 0..7 (uses w[0..23]); w[0..7] die after this
    {
        float acc[8];
        #pragma unroll
        for (int u = 0; u < 8; u++) {
            float a = 0.f;
            #pragma unroll
            for (int j = 0; j < CKLEN; j++)
                a = fmaf(k[j], w[u + j], a);
            acc[u] = a;
        }
        o[0] = make_float4(acc[0], acc[1], acc[2], acc[3]);
        o[1] = make_float4(acc[4], acc[5], acc[6], acc[7]);
    }

    // phase B: outputs 8..15 (uses w[8..31])
    {
        float acc[8];
        #pragma unroll
        for (int u = 0; u < 8; u++) {
            float a = 0.f;
            #pragma unroll
            for (int j = 0; j < CKLEN; j++)
                a = fmaf(k[j], w[8 + u + j], a);
            acc[u] = a;
        }
        o[2] = make_float4(acc[0], acc[1], acc[2], acc[3]);
        o[3] = make_float4(acc[4], acc[5], acc[6], acc[7]);
    }
}

// ---------------------------------------------------------------------------
// Launch
// ---------------------------------------------------------------------------
extern "C" void kernel_launch(void* const* d_in, const int* in_sizes, int n_in,
                              void* d_out, int out_size)
{
    const float* x       = (const float*)d_in[0];   // [4096, 8192] f32
    const int*   g       = (const int*)  d_in[1];   // [4096] i32
    const float* kernels = (const float*)d_in[2];   // [81, 5] f32
    float*       out     = (float*)d_out;           // [4096, 1, 8192] f32

    compose_kernel<<<BB / NTHR, NTHR>>>(g, kernels);
    conv_main<<<BB * TILES_PER_ROW, NTHR>>>(x, out);
}

// round 5
// speedup vs baseline: 1.6379x; 1.2102x over previous
#include <cuda_runtime.h>

#define BB      4096
#define DD      8192
#define KK      5
#define GS      40
#define CKLEN   17
#define NTHR    256
#define TILE    2048                    // outputs per block
#define TILES_PER_ROW (DD / TILE)       // 4

// Composed per-row 17-tap kernels (4096 * 17 * 4B = 278 KB, L2-resident)
__device__ float g_ck[BB * CKLEN];

// ---------------------------------------------------------------------------
// Kernel 1: compose each row's 17-tap kernel. 16 blocks x 256 threads,
// one row per thread; each block redundantly reduces max_it over g (L2 hits).
// ---------------------------------------------------------------------------
__global__ void __launch_bounds__(NTHR)
compose_kernel(const int* __restrict__ g, const float* __restrict__ kernels)
{
    __shared__ int s_red[NTHR / 32];
    const int t = threadIdx.x;
    const int b = blockIdx.x * NTHR + t;

    int m = 0;
    #pragma unroll 4
    for (int i = t; i < BB; i += NTHR) {
        int gv = g[i];
        int av = gv < 0 ? -gv : gv;
        m = max(m, av / GS);
    }
    #pragma unroll
    for (int o = 16; o > 0; o >>= 1)
        m = max(m, __shfl_xor_sync(0xffffffffu, m, o));
    if ((t & 31) == 0) s_red[t >> 5] = m;
    __syncthreads();
    int max_it = s_red[0];
    #pragma unroll
    for (int w = 1; w < NTHR / 32; w++) max_it = max(max_it, s_red[w]);

    float idk[KK], posk[KK], negk[KK];
    #pragma unroll
    for (int j = 0; j < KK; j++) {
        idk[j]  = __ldg(kernels + 40 * KK + j);
        posk[j] = __ldg(kernels + 80 * KK + j);
        negk[j] = __ldg(kernels + 0  * KK + j);
    }

    int gv  = g[b];
    int sgn = (gv > 0) - (gv < 0);
    int av  = gv < 0 ? -gv : gv;
    int it  = av / GS;
    int rem = av - it * GS;

    int fidx = rem * sgn + 40;
    float fink[KK];
    #pragma unroll
    for (int j = 0; j < KK; j++) fink[j] = __ldg(kernels + fidx * KK + j);

    float maxk[KK];
    #pragma unroll
    for (int j = 0; j < KK; j++)
        maxk[j] = (sgn > 0) ? posk[j] : ((sgn < 0) ? negk[j] : idk[j]);

    float c[CKLEN];
    #pragma unroll
    for (int p = 0; p < CKLEN; p++) c[p] = 0.f;
    c[8] = 1.f;

    #pragma unroll
    for (int stage = 0; stage < 4; stage++) {
        float kk[KK];
        bool skip = false;
        if (stage == 3) {
            #pragma unroll
            for (int j = 0; j < KK; j++) kk[j] = fink[j];
        } else if (stage < it) {
            #pragma unroll
            for (int j = 0; j < KK; j++) kk[j] = maxk[j];
        } else if (stage < max_it) {
            #pragma unroll
            for (int j = 0; j < KK; j++) kk[j] = idk[j];
        } else {
            skip = true;
        }
        if (!skip) {
            float nc[CKLEN];
            #pragma unroll
            for (int p = 0; p < CKLEN; p++) {
                float a = 0.f;
                #pragma unroll
                for (int j = 0; j < KK; j++) {
                    int q = p - j + 2;
                    if (q >= 0 && q < CKLEN) a = fmaf(kk[j], c[q], a);
                }
                nc[p] = a;
            }
            #pragma unroll
            for (int p = 0; p < CKLEN; p++) c[p] = nc[p];
        }
    }

    #pragma unroll
    for (int p = 0; p < CKLEN; p++) g_ck[b * CKLEN + p] = c[p];
}

// ---------------------------------------------------------------------------
// Kernel 2: single-pass 17-tap circular correlation, lane-interleaved float4s.
// Thread (warp w, lane l), round r computes the float4 of outputs at
// float4-index  w*64 + r*32 + l  within the block's 2048-output tile.
// Every LDG.128 / STG.128 is a fully coalesced 512B warp access.
// ---------------------------------------------------------------------------
__global__ void __launch_bounds__(NTHR)
conv_main(const float* __restrict__ x, float* __restrict__ out)
{
    const int bid  = blockIdx.x;
    const int b    = bid >> 2;              // TILES_PER_ROW = 4
    const int tile = bid & 3;
    const int lane = threadIdx.x & 31;
    const int warp = threadIdx.x >> 5;

    const float* __restrict__ xr = x + (size_t)b * DD;
    float* __restrict__ orow     = out + (size_t)b * DD;

    // row kernel: uniform across the block (broadcast loads)
    float k[CKLEN];
    const float* ckp = g_ck + b * CKLEN;
    #pragma unroll
    for (int j = 0; j < CKLEN; j++) k[j] = __ldg(ckp + j);

    const int base4 = tile * (TILE / 4) + warp * 64 + lane;  // float4 index, round 0

    #pragma unroll
    for (int r = 0; r < 2; r++) {
        const int d = (base4 + r * 32) * 4;   // first output of this float4

        // window x[d-8 .. d+11]: 5 overlapping, per-float4-wrapped LDG.128
        float w[20];
        #pragma unroll
        for (int q = 0; q < 5; q++) {
            int idx = d - 8 + 4 * q;
            idx = (idx < 0) ? idx + DD : ((idx >= DD) ? idx - DD : idx);
            float4 v = __ldg(reinterpret_cast<const float4*>(xr + idx));
            w[4 * q + 0] = v.x;
            w[4 * q + 1] = v.y;
            w[4 * q + 2] = v.z;
            w[4 * q + 3] = v.w;
        }

        // out[d+i] = sum_p k[p] * w[i+p]
        float4 o;
        float a0 = 0.f, a1 = 0.f, a2 = 0.f, a3 = 0.f;
        #pragma unroll
        for (int p = 0; p < CKLEN; p++) {
            a0 = fmaf(k[p], w[p + 0], a0);
            a1 = fmaf(k[p], w[p + 1], a1);
            a2 = fmaf(k[p], w[p + 2], a2);
            a3 = fmaf(k[p], w[p + 3], a3);
        }
        o.x = a0; o.y = a1; o.z = a2; o.w = a3;

        *reinterpret_cast<float4*>(orow + d) = o;
    }
}

// ---------------------------------------------------------------------------
// Launch
// ---------------------------------------------------------------------------
extern "C" void kernel_launch(void* const* d_in, const int* in_sizes, int n_in,
                              void* d_out, int out_size)
{
    const float* x       = (const float*)d_in[0];   // [4096, 8192] f32
    const int*   g       = (const int*)  d_in[1];   // [4096] i32
    const float* kernels = (const float*)d_in[2];   // [81, 5] f32
    float*       out     = (float*)d_out;           // [4096, 1, 8192] f32

    compose_kernel<<<BB / NTHR, NTHR>>>(g, kernels);
    conv_main<<<BB * TILES_PER_ROW, NTHR>>>(x, out);
}

// round 6
// speedup vs baseline: 1.6524x; 1.0089x over previous
#include <cuda_runtime.h>

#define BB      4096
#define DD      8192
#define KK      5
#define GS      40
#define CKLEN   17
#define NTHR    256
#define TILE    2048                    // outputs per block
#define TILES_PER_ROW (DD / TILE)       // 4

#define CNTHR   128                     // compose block size
#define CBLK    (BB / CNTHR)            // 32 compose blocks

// Composed per-row 17-tap kernels (4096 * 17 * 4B = 278 KB, L2-resident)
__device__ float g_ck[BB * CKLEN];

// ---------------------------------------------------------------------------
// Kernel 1: compose each row's 17-tap kernel. 32 blocks x 128 threads,
// one row per thread; each block redundantly reduces max_it over g (L2 hits).
// ---------------------------------------------------------------------------
__global__ void __launch_bounds__(CNTHR)
compose_kernel(const int* __restrict__ g, const float* __restrict__ kernels)
{
    __shared__ int s_red[CNTHR / 32];
    const int t = threadIdx.x;
    const int b = blockIdx.x * CNTHR + t;

    int m = 0;
    #pragma unroll 8
    for (int i = t; i < BB; i += CNTHR) {
        int gv = g[i];
        int av = gv < 0 ? -gv : gv;
        m = max(m, av / GS);
    }
    #pragma unroll
    for (int o = 16; o > 0; o >>= 1)
        m = max(m, __shfl_xor_sync(0xffffffffu, m, o));
    if ((t & 31) == 0) s_red[t >> 5] = m;
    __syncthreads();
    int max_it = s_red[0];
    #pragma unroll
    for (int w = 1; w < CNTHR / 32; w++) max_it = max(max_it, s_red[w]);

    float idk[KK], posk[KK], negk[KK];
    #pragma unroll
    for (int j = 0; j < KK; j++) {
        idk[j]  = __ldg(kernels + 40 * KK + j);
        posk[j] = __ldg(kernels + 80 * KK + j);
        negk[j] = __ldg(kernels + 0  * KK + j);
    }

    int gv  = g[b];
    int sgn = (gv > 0) - (gv < 0);
    int av  = gv < 0 ? -gv : gv;
    int it  = av / GS;
    int rem = av - it * GS;

    int fidx = rem * sgn + 40;
    float fink[KK];
    #pragma unroll
    for (int j = 0; j < KK; j++) fink[j] = __ldg(kernels + fidx * KK + j);

    float maxk[KK];
    #pragma unroll
    for (int j = 0; j < KK; j++)
        maxk[j] = (sgn > 0) ? posk[j] : ((sgn < 0) ? negk[j] : idk[j]);

    float c[CKLEN];
    #pragma unroll
    for (int p = 0; p < CKLEN; p++) c[p] = 0.f;
    c[8] = 1.f;

    #pragma unroll
    for (int stage = 0; stage < 4; stage++) {
        float kk[KK];
        bool skip = false;
        if (stage == 3) {
            #pragma unroll
            for (int j = 0; j < KK; j++) kk[j] = fink[j];
        } else if (stage < it) {
            #pragma unroll
            for (int j = 0; j < KK; j++) kk[j] = maxk[j];
        } else if (stage < max_it) {
            #pragma unroll
            for (int j = 0; j < KK; j++) kk[j] = idk[j];
        } else {
            skip = true;
        }
        if (!skip) {
            float nc[CKLEN];
            #pragma unroll
            for (int p = 0; p < CKLEN; p++) {
                float a = 0.f;
                #pragma unroll
                for (int j = 0; j < KK; j++) {
                    int q = p - j + 2;
                    if (q >= 0 && q < CKLEN) a = fmaf(kk[j], c[q], a);
                }
                nc[p] = a;
            }
            #pragma unroll
            for (int p = 0; p < CKLEN; p++) c[p] = nc[p];
        }
    }

    #pragma unroll
    for (int p = 0; p < CKLEN; p++) g_ck[b * CKLEN + p] = c[p];
}

// ---------------------------------------------------------------------------
// Kernel 2: single-pass 17-tap circular correlation, lane-interleaved float4s.
// Wrap test hoisted per-round: only 2 float4s per ROW (d=0, d=DD-4) take the
// wrapped path; everyone else does 5 immediate-offset LDG.128 off one base.
// ---------------------------------------------------------------------------
__global__ void __launch_bounds__(NTHR)
conv_main(const float* __restrict__ x, float* __restrict__ out)
{
    const int bid  = blockIdx.x;
    const int b    = bid >> 2;              // TILES_PER_ROW = 4
    const int tile = bid & 3;
    const int lane = threadIdx.x & 31;
    const int warp = threadIdx.x >> 5;

    const float* __restrict__ xr = x + (size_t)b * DD;
    float* __restrict__ orow     = out + (size_t)b * DD;

    // row kernel: uniform across the block (broadcast loads)
    float k[CKLEN];
    const float* ckp = g_ck + b * CKLEN;
    #pragma unroll
    for (int j = 0; j < CKLEN; j++) k[j] = __ldg(ckp + j);

    const int base4 = tile * (TILE / 4) + warp * 64 + lane;  // float4 index, round 0

    #pragma unroll
    for (int r = 0; r < 2; r++) {
        const int d = (base4 + r * 32) * 4;   // first output of this float4

        float w[20];                          // x[d-8 .. d+11]
        if ((unsigned)(d - 8) <= (unsigned)(DD - 20)) {
            // fast path: 5 LDG.128 at immediate offsets off one base pointer
            const float4* p = reinterpret_cast<const float4*>(xr + d - 8);
            #pragma unroll
            for (int q = 0; q < 5; q++) {
                float4 v = __ldg(p + q);
                w[4 * q + 0] = v.x;
                w[4 * q + 1] = v.y;
                w[4 * q + 2] = v.z;
                w[4 * q + 3] = v.w;
            }
        } else {
            // wrap path: exactly 2 float4s per row land here
            #pragma unroll
            for (int q = 0; q < 5; q++) {
                int idx = d - 8 + 4 * q;
                idx = (idx < 0) ? idx + DD : ((idx >= DD) ? idx - DD : idx);
                float4 v = __ldg(reinterpret_cast<const float4*>(xr + idx));
                w[4 * q + 0] = v.x;
                w[4 * q + 1] = v.y;
                w[4 * q + 2] = v.z;
                w[4 * q + 3] = v.w;
            }
        }

        // out[d+i] = sum_p k[p] * w[i+p]
        float a0 = 0.f, a1 = 0.f, a2 = 0.f, a3 = 0.f;
        #pragma unroll
        for (int p = 0; p < CKLEN; p++) {
            a0 = fmaf(k[p], w[p + 0], a0);
            a1 = fmaf(k[p], w[p + 1], a1);
            a2 = fmaf(k[p], w[p + 2], a2);
            a3 = fmaf(k[p], w[p + 3], a3);
        }

        __stcs(reinterpret_cast<float4*>(orow + d), make_float4(a0, a1, a2, a3));
    }
}

// ---------------------------------------------------------------------------
// Launch
// ---------------------------------------------------------------------------
extern "C" void kernel_launch(void* const* d_in, const int* in_sizes, int n_in,
                              void* d_out, int out_size)
{
    const float* x       = (const float*)d_in[0];   // [4096, 8192] f32
    const int*   g       = (const int*)  d_in[1];   // [4096] i32
    const float* kernels = (const float*)d_in[2];   // [81, 5] f32
    float*       out     = (float*)d_out;           // [4096, 1, 8192] f32

    compose_kernel<<<CBLK, CNTHR>>>(g, kernels);
    conv_main<<<BB * TILES_PER_ROW, NTHR>>>(x, out);
}